// round 10
// baseline (speedup 1.0000x reference)
#include <cuda_runtime.h>
#include <cstdint>

#define BATCH 128
#define NNODE 2048
#define ND 128      // NODE_DIM
#define QD 256      // QUERY_DIM
#define OD 256      // OUT_DIM
#define NW 32       // warps per CTA
#define NT (NW*32)  // 1024 threads
#define TILE_NODES 64
#define TILE_BYTES (TILE_NODES*ND*4)   // 32768
#define NTILES (NNODE/TILE_NODES)      // 32
#define STAGES 4
#define DYN_SMEM (STAGES*TILE_BYTES)   // 131072

__device__ __forceinline__ unsigned smem_u32(const void* p) {
    unsigned a;
    asm("{ .reg .u64 t; cvta.to.shared.u64 t, %1; cvt.u32.u64 %0, t; }" : "=r"(a) : "l"(p));
    return a;
}
__device__ __forceinline__ void mbar_init(unsigned addr, unsigned cnt) {
    asm volatile("mbarrier.init.shared.b64 [%0], %1;" :: "r"(addr), "r"(cnt) : "memory");
}
__device__ __forceinline__ void mbar_expect_tx(unsigned addr, unsigned bytes) {
    asm volatile("mbarrier.arrive.expect_tx.shared.b64 _, [%0], %1;" :: "r"(addr), "r"(bytes) : "memory");
}
__device__ __forceinline__ void bulk_g2s(unsigned dst, const void* src, unsigned bytes, unsigned mbar) {
    asm volatile("cp.async.bulk.shared::cta.global.mbarrier::complete_tx::bytes [%0], [%1], %2, [%3];"
                 :: "r"(dst), "l"(src), "r"(bytes), "r"(mbar) : "memory");
}
__device__ __forceinline__ void mbar_wait(unsigned addr, unsigned parity) {
    asm volatile(
        "{\n\t.reg .pred P;\n\t"
        "WAIT_%=:\n\t"
        "mbarrier.try_wait.parity.acquire.cta.shared::cta.b64 P, [%0], %1, 0x989680;\n\t"
        "@P bra.uni DONE_%=;\n\t"
        "bra.uni WAIT_%=;\n\t"
        "DONE_%=:\n\t}"
        :: "r"(addr), "r"(parity) : "memory");
}

__global__ __launch_bounds__(NT, 1)
void gar_fused_kernel(const float* __restrict__ fp_vec,
                      const float* __restrict__ node_mat,
                      const void*  __restrict__ mask,
                      const float* __restrict__ Wq1,
                      const float* __restrict__ Wq2,
                      const float* __restrict__ Wk,
                      const float* __restrict__ Wv,
                      const float* __restrict__ lambda_logit,
                      const float* __restrict__ gamma,
                      const float* __restrict__ beta,
                      float* __restrict__ out)
{
    extern __shared__ __align__(128) char dynbuf[];   // STAGES x 32KB tile ring

    __shared__ __align__(16) float q1s[ND], q2s[ND], q1t[ND], q2t[ND];
    __shared__ __align__(16) float pads[NNODE];                 // 8 KB
    __shared__ __align__(16) float wacc1[NW*ND], wacc2[NW*ND];  // 32 KB
    __shared__ __align__(16) float ztd[ND];
    __shared__ __align__(8)  unsigned long long mbar[STAGES];
    __shared__ float wl1[NW], wl2[NW];
    __shared__ float red[NW];
    __shared__ int   smode;

    const int t = threadIdx.x;
    const int b = blockIdx.x;
    const int w = t >> 5, l = t & 31;

    const char* src = (const char*)node_mat + (size_t)b * NNODE * ND * 4;
    const unsigned mbar0 = smem_u32(&mbar[0]);
    const unsigned dbase = smem_u32(dynbuf);

    // ---- init barriers + start the TMA pipeline ASAP ----
    if (t == 0) {
        smode = 0;
        #pragma unroll
        for (int s = 0; s < STAGES; s++) mbar_init(mbar0 + s*8, 1);
    }
    __syncthreads();
    if (t == 0) {
        #pragma unroll
        for (int s = 0; s < STAGES; s++) {
            mbar_expect_tx(mbar0 + s*8, TILE_BYTES);
            bulk_g2s(dbase + s*TILE_BYTES, src + (size_t)s*TILE_BYTES, TILE_BYTES, mbar0 + s*8);
        }
    }

    // ---- mask dtype sniff (overlapped with TMA) ----
    if (t < 512) {
        const unsigned int* mw = (const unsigned int*)mask;
        unsigned int v = mw[b * 512 + t];
        int f = 0;
        if (v == 0x3F800000u)            f = 2;   // fp32 one
        else if (v != 0u && v != 1u)     f = 1;   // byte-packed bool signature
        if (f) atomicOr(&smode, f);
    }

    // ---- q1 = fp@Wq1^T, q2 = fp@Wq2^T ----
    {
        const float4* fp4 = (const float4*)(fp_vec + b*QD);
        if (t < 2*ND) {
            int e = t & (ND-1);
            const float4* Wr = (const float4*)((t < ND ? Wq1 : Wq2) + e*QD);
            float s = 0.f;
            #pragma unroll 8
            for (int q4 = 0; q4 < QD/4; q4++) {
                float4 a = fp4[q4], ww = Wr[q4];
                s += a.x*ww.x + a.y*ww.y + a.z*ww.z + a.w*ww.w;
            }
            if (t < ND) q1s[e] = s; else q2s[e] = s;
        }
    }
    __syncthreads();

    // ---- pads[] from mask; q1t/q2t = (q@Wk)*inv_scale ----
    {
        const int mode = smode;
        const int*           mi  = (const int*)mask           + (size_t)b * NNODE;
        const unsigned char* mu8 = (const unsigned char*)mask + (size_t)b * NNODE;
        const float*         mf  = (const float*)mask         + (size_t)b * NNODE;
        for (int n = t; n < NNODE; n += NT) {
            bool valid;
            if (mode & 1)      valid = mu8[n] != 0;
            else if (mode & 2) valid = mf[n]  != 0.f;
            else               valid = mi[n]  != 0;
            pads[n] = valid ? 0.f : -1e9f;
        }
    }
    if (t < 2*ND) {
        const float inv_scale = 0.08838834764831845f;  // 1/sqrt(128)
        int d = t & (ND-1);
        const float* qs = (t < ND) ? q1s : q2s;
        float s = 0.f;
        #pragma unroll 8
        for (int e = 0; e < ND; e++) s += qs[e] * Wk[e*ND + d];
        s *= inv_scale;
        if (t < ND) q1t[d] = s; else q2t[d] = s;
    }
    __syncthreads();

    const float4 q1r = ((const float4*)q1t)[l];   // lane owns dims [4l, 4l+4)
    const float4 q2r = ((const float4*)q2t)[l];

    float4 c1 = make_float4(0.f,0.f,0.f,0.f);
    float4 c2 = c1;
    float L1 = 0.f, L2 = 0.f;

    // ---- main loop: consume 32KB tiles from the smem ring (2 nodes/warp/tile) ----
    for (int tl = 0; tl < NTILES; tl++) {
        const int s  = tl & (STAGES-1);
        const unsigned ph = (tl >> 2) & 1;
        mbar_wait(mbar0 + s*8, ph);

        const float4* tb = (const float4*)(dynbuf + s*TILE_BYTES);
        const int n0 = w*2;                      // node within tile
        float4 x0 = tb[(n0+0)*32 + l];           // conflict-free LDS.128
        float4 x1 = tb[(n0+1)*32 + l];
        float pd0 = pads[tl*TILE_NODES + n0];
        float pd1 = pads[tl*TILE_NODES + n0 + 1];

        float p10 = x0.x*q1r.x + x0.y*q1r.y + x0.z*q1r.z + x0.w*q1r.w;
        float p20 = x0.x*q2r.x + x0.y*q2r.y + x0.z*q2r.z + x0.w*q2r.w;
        float p11 = x1.x*q1r.x + x1.y*q1r.y + x1.z*q1r.z + x1.w*q1r.w;
        float p21 = x1.x*q2r.x + x1.y*q2r.y + x1.z*q2r.z + x1.w*q2r.w;

        #pragma unroll
        for (int o = 16; o > 0; o >>= 1) {
            p10 += __shfl_xor_sync(0xffffffffu, p10, o);
            p20 += __shfl_xor_sync(0xffffffffu, p20, o);
            p11 += __shfl_xor_sync(0xffffffffu, p11, o);
            p21 += __shfl_xor_sync(0xffffffffu, p21, o);
        }

        float e10 = __expf(p10 + pd0);   // |s| <~ 2, exp-no-max is exact-safe; masked -> 0
        float e20 = __expf(p20 + pd0);
        float e11 = __expf(p11 + pd1);
        float e21 = __expf(p21 + pd1);
        L1 += e10 + e11;
        L2 += e20 + e21;

        c1.x += e10*x0.x + e11*x1.x;  c1.y += e10*x0.y + e11*x1.y;
        c1.z += e10*x0.z + e11*x1.z;  c1.w += e10*x0.w + e11*x1.w;
        c2.x += e20*x0.x + e21*x1.x;  c2.y += e20*x0.y + e21*x1.y;
        c2.z += e20*x0.z + e21*x1.z;  c2.w += e20*x0.w + e21*x1.w;

        __syncthreads();                          // everyone done reading stage s
        if (t == 0 && tl + STAGES < NTILES) {     // refill stage s with tile tl+4
            mbar_expect_tx(mbar0 + s*8, TILE_BYTES);
            bulk_g2s(dbase + s*TILE_BYTES, src + (size_t)(tl+STAGES)*TILE_BYTES,
                     TILE_BYTES, mbar0 + s*8);
        }
    }

    // ---- publish per-warp partials (lane-uniform L, per-lane 4-dim acc) ----
    ((float4*)(wacc1 + w*ND))[l] = c1;
    ((float4*)(wacc2 + w*ND))[l] = c2;
    if (l == 0) { wl1[w] = L1; wl2[w] = L2; }
    __syncthreads();

    // ---- linear merge across warps ----
    if (t < ND) {
        float z1 = 0.f, z2 = 0.f, tL1 = 0.f, tL2 = 0.f;
        #pragma unroll
        for (int k = 0; k < NW; k++) {
            z1  += wacc1[k*ND + t];
            z2  += wacc2[k*ND + t];
            tL1 += wl1[k];
            tL2 += wl2[k];
        }
        float lam = 0.8f + 0.2f / (1.f + __expf(-lambda_logit[0]));
        ztd[t] = z1/tL1 - lam*(z2/tL2);
    }
    __syncthreads();

    // ---- z = ztd @ Wv^T (one output per thread, t<256) ----
    float zv = 0.f;
    if (t < OD) {
        const float4* wr  = (const float4*)(Wv + t*ND);
        const float4* zt4 = (const float4*)ztd;
        float s = 0.f;
        #pragma unroll 8
        for (int d4 = 0; d4 < ND/4; d4++) {
            float4 a = zt4[d4], ww = wr[d4];
            s += a.x*ww.x + a.y*ww.y + a.z*ww.z + a.w*ww.w;
        }
        zv = s;
    }

    // ---- LayerNorm over OD=256 ----
    float s = (t < OD) ? zv : 0.f;
    #pragma unroll
    for (int o = 16; o > 0; o >>= 1) s += __shfl_xor_sync(0xffffffffu, s, o);
    if (l == 0) red[w] = s;
    __syncthreads();
    float tot = 0.f;
    #pragma unroll
    for (int k = 0; k < NW; k++) tot += red[k];
    float mu = tot / OD;

    float dv = (t < OD) ? (zv - mu) : 0.f;
    float sq = dv*dv;
    __syncthreads();   // red reuse
    #pragma unroll
    for (int o = 16; o > 0; o >>= 1) sq += __shfl_xor_sync(0xffffffffu, sq, o);
    if (l == 0) red[w] = sq;
    __syncthreads();
    float tot2 = 0.f;
    #pragma unroll
    for (int k = 0; k < NW; k++) tot2 += red[k];
    float var = tot2 / OD;
    float inv = rsqrtf(var + 1e-5f);

    if (t < OD) out[b*OD + t] = (zv - mu)*inv*gamma[t] + beta[t];
}

extern "C" void kernel_launch(void* const* d_in, const int* in_sizes, int n_in,
                              void* d_out, int out_size) {
    cudaFuncSetAttribute(gar_fused_kernel,
                         cudaFuncAttributeMaxDynamicSharedMemorySize, DYN_SMEM);
    gar_fused_kernel<<<BATCH, NT, DYN_SMEM>>>(
        (const float*)d_in[0],   // fp_vec
        (const float*)d_in[1],   // node_mat
        d_in[2],                 // mask (dtype auto-detected)
        (const float*)d_in[3],   // Wq1
        (const float*)d_in[4],   // Wq2
        (const float*)d_in[5],   // Wk
        (const float*)d_in[6],   // Wv
        (const float*)d_in[7],   // lambda_logit
        (const float*)d_in[8],   // gamma
        (const float*)d_in[9],   // beta
        (float*)d_out);
}

// round 11
// speedup vs baseline: 1.0373x; 1.0373x over previous
#include <cuda_runtime.h>
#include <cstdint>

#define BATCH 128
#define NNODE 2048
#define ND 128      // NODE_DIM
#define QD 256      // QUERY_DIM
#define OD 256      // OUT_DIM
#define SLICES 2
#define SLICE_NODES (NNODE/SLICES)          // 1024
#define K1_WARPS 8
#define K1_THREADS 256
#define NODES_PER_WARP (SLICE_NODES/K1_WARPS)  // 128
#define BT 8                                 // nodes per register batch
#define NB (NODES_PER_WARP/BT)               // 16 batches
#define PSTRIDE 272                          // floats per partial record (16B-friendly)

__device__ __align__(16) float g_q1t[BATCH*ND];
__device__ __align__(16) float g_q2t[BATCH*ND];
__device__ __align__(16) float g_part[BATCH*SLICES*PSTRIDE];

// ---------------- kernel 0: per-batch query precompute ----------------
__global__ __launch_bounds__(256)
void k0_qprep(const float* __restrict__ fp_vec,
              const float* __restrict__ Wq1,
              const float* __restrict__ Wq2,
              const float* __restrict__ Wk)
{
    __shared__ __align__(16) float q1s[ND], q2s[ND];
    const int t = threadIdx.x, b = blockIdx.x;
    {
        const float4* fp4 = (const float4*)(fp_vec + b*QD);
        const int e = t & (ND-1);
        const float4* Wr = (const float4*)((t < ND ? Wq1 : Wq2) + e*QD);
        float s = 0.f;
        #pragma unroll 8
        for (int q4 = 0; q4 < QD/4; q4++) {
            float4 a = fp4[q4], w = Wr[q4];
            s += a.x*w.x + a.y*w.y + a.z*w.z + a.w*w.w;
        }
        if (t < ND) q1s[e] = s; else q2s[e] = s;
    }
    __syncthreads();
    {
        const int d = t & (ND-1);
        const float* qs = (t < ND) ? q1s : q2s;
        float s = 0.f;
        #pragma unroll 8
        for (int e = 0; e < ND; e++) s += qs[e] * Wk[e*ND + d];
        s *= 0.08838834764831845f;   // 1/sqrt(128)
        if (t < ND) g_q1t[b*ND + d] = s; else g_q2t[b*ND + d] = s;
    }
}

// ---------------- kernel 1: streaming attention partials ----------------
#define COMPUTE(X, ii) { \
    float p1[BT], p2[BT]; \
    _Pragma("unroll") for (int j = 0; j < BT; j++) { \
        p1[j] = X[j].x*q1r.x + X[j].y*q1r.y + X[j].z*q1r.z + X[j].w*q1r.w; \
        p2[j] = X[j].x*q2r.x + X[j].y*q2r.y + X[j].z*q2r.z + X[j].w*q2r.w; } \
    _Pragma("unroll") for (int o = 16; o > 0; o >>= 1) { \
        _Pragma("unroll") for (int j = 0; j < BT; j++) { \
            p1[j] += __shfl_xor_sync(0xffffffffu, p1[j], o); \
            p2[j] += __shfl_xor_sync(0xffffffffu, p2[j], o); } } \
    _Pragma("unroll") for (int j = 0; j < BT; j++) { \
        float pd = pads[pbase + (ii)*BT + j]; \
        float e1 = __expf(p1[j] + pd); \
        float e2 = __expf(p2[j] + pd); \
        L1 += e1; L2 += e2; \
        c1.x += e1*X[j].x; c1.y += e1*X[j].y; c1.z += e1*X[j].z; c1.w += e1*X[j].w; \
        c2.x += e2*X[j].x; c2.y += e2*X[j].y; c2.z += e2*X[j].z; c2.w += e2*X[j].w; } }

__global__ __launch_bounds__(K1_THREADS, 2)
void k1_stream(const float* __restrict__ node_mat,
               const void*  __restrict__ mask)
{
    __shared__ float pads[SLICE_NODES];                               // 4 KB
    __shared__ __align__(16) float wacc1[K1_WARPS*ND], wacc2[K1_WARPS*ND];  // 8 KB
    __shared__ float wl1[K1_WARPS], wl2[K1_WARPS];
    __shared__ int smode;

    const int t = threadIdx.x;
    const int bid = blockIdx.x;
    const int b = bid >> 1, q = bid & 1;
    const int w = t >> 5, l = t & 31;

    if (t == 0) smode = 0;
    __syncthreads();
    // mask dtype sniff: words [b*512, b*512+512) — in-bounds under u8 hypothesis (256KB)
    {
        const unsigned* mw = (const unsigned*)mask;
        #pragma unroll
        for (int r = 0; r < 2; r++) {
            unsigned v = mw[b*512 + t + r*256];
            int f = 0;
            if (v == 0x3F800000u)        f = 2;   // fp32 one
            else if (v != 0u && v != 1u) f = 1;   // byte-packed bool signature
            if (f) atomicOr(&smode, f);
        }
    }
    __syncthreads();
    {
        const int mode = smode;
        const size_t off = (size_t)b*NNODE + q*SLICE_NODES;
        const int*           mi  = (const int*)mask           + off;
        const unsigned char* mu8 = (const unsigned char*)mask + off;
        const float*         mf  = (const float*)mask         + off;
        #pragma unroll
        for (int r = 0; r < SLICE_NODES/K1_THREADS; r++) {
            int n = t + r*K1_THREADS;
            bool valid;
            if (mode & 1)      valid = mu8[n] != 0;
            else if (mode & 2) valid = mf[n]  != 0.f;
            else               valid = mi[n]  != 0;
            pads[n] = valid ? 0.f : -1e9f;
        }
    }
    const float4 q1r = ((const float4*)(g_q1t + b*ND))[l];   // lane owns dims [4l,4l+4)
    const float4 q2r = ((const float4*)(g_q2t + b*ND))[l];
    __syncthreads();

    // this warp's contiguous 128-node region
    const float4* p = (const float4*)node_mat
        + ((size_t)b*NNODE + q*SLICE_NODES + w*NODES_PER_WARP) * (ND/4) + l;
    const int pbase = w*NODES_PER_WARP;

    float4 c1 = make_float4(0.f,0.f,0.f,0.f), c2 = c1;
    float L1 = 0.f, L2 = 0.f;

    float4 A[BT], Bf[BT];
    #pragma unroll
    for (int j = 0; j < BT; j++) A[j] = p[j*32];     // batch 0

    for (int i = 0; i < NB; i += 2) {
        #pragma unroll
        for (int j = 0; j < BT; j++) Bf[j] = p[((i+1)*BT + j)*32];   // prefetch batch i+1
        COMPUTE(A, i)
        if (i + 2 < NB) {
            #pragma unroll
            for (int j = 0; j < BT; j++) A[j] = p[((i+2)*BT + j)*32]; // prefetch batch i+2
        }
        COMPUTE(Bf, i+1)
    }

    // publish per-warp partials
    ((float4*)(wacc1 + w*ND))[l] = c1;
    ((float4*)(wacc2 + w*ND))[l] = c2;
    if (l == 0) { wl1[w] = L1; wl2[w] = L2; }
    __syncthreads();

    if (t < ND) {
        float z1 = 0.f, z2 = 0.f;
        #pragma unroll
        for (int k = 0; k < K1_WARPS; k++) { z1 += wacc1[k*ND + t]; z2 += wacc2[k*ND + t]; }
        float* P = g_part + (size_t)bid*PSTRIDE;
        P[t] = z1; P[ND + t] = z2;
    }
    if (t == 0) {
        float tL1 = 0.f, tL2 = 0.f;
        #pragma unroll
        for (int k = 0; k < K1_WARPS; k++) { tL1 += wl1[k]; tL2 += wl2[k]; }
        float* P = g_part + (size_t)bid*PSTRIDE;
        P[2*ND] = tL1; P[2*ND+1] = tL2;
    }
}

// ---------------- kernel 2: merge + Wv + LayerNorm ----------------
__global__ __launch_bounds__(256)
void k2_epi(const float* __restrict__ Wv,
            const float* __restrict__ lambda_logit,
            const float* __restrict__ gamma,
            const float* __restrict__ beta,
            float* __restrict__ out)
{
    __shared__ __align__(16) float ztd[ND];
    __shared__ float red[8];
    const int t = threadIdx.x, b = blockIdx.x;
    const int w = t >> 5, l = t & 31;

    const float* P0 = g_part + (size_t)(b*2)  *PSTRIDE;
    const float* P1 = P0 + PSTRIDE;
    if (t < ND) {
        float z1 = P0[t]      + P1[t];
        float z2 = P0[ND+t]   + P1[ND+t];
        float L1 = P0[2*ND]   + P1[2*ND];
        float L2 = P0[2*ND+1] + P1[2*ND+1];
        float lam = 0.8f + 0.2f / (1.f + __expf(-lambda_logit[0]));
        ztd[t] = z1/L1 - lam*(z2/L2);
    }
    __syncthreads();

    float zv = 0.f;
    {
        const float4* wr = (const float4*)(Wv + t*ND);
        const float4* z4 = (const float4*)ztd;
        #pragma unroll 8
        for (int d4 = 0; d4 < ND/4; d4++) {
            float4 a = z4[d4], ww = wr[d4];
            zv += a.x*ww.x + a.y*ww.y + a.z*ww.z + a.w*ww.w;
        }
    }
    // LayerNorm over OD=256 (all 256 threads hold one element)
    float s = zv;
    #pragma unroll
    for (int o = 16; o > 0; o >>= 1) s += __shfl_xor_sync(0xffffffffu, s, o);
    if (l == 0) red[w] = s;
    __syncthreads();
    float tot = 0.f;
    #pragma unroll
    for (int k = 0; k < 8; k++) tot += red[k];
    float mu = tot / OD;

    float dv = zv - mu;
    float sq = dv*dv;
    __syncthreads();   // red reuse
    #pragma unroll
    for (int o = 16; o > 0; o >>= 1) sq += __shfl_xor_sync(0xffffffffu, sq, o);
    if (l == 0) red[w] = sq;
    __syncthreads();
    float tot2 = 0.f;
    #pragma unroll
    for (int k = 0; k < 8; k++) tot2 += red[k];
    float inv = rsqrtf(tot2 / OD + 1e-5f);

    out[b*OD + t] = dv*inv*gamma[t] + beta[t];
}

extern "C" void kernel_launch(void* const* d_in, const int* in_sizes, int n_in,
                              void* d_out, int out_size) {
    const float* fp_vec   = (const float*)d_in[0];
    const float* node_mat = (const float*)d_in[1];
    const void*  mask     = d_in[2];
    const float* Wq1      = (const float*)d_in[3];
    const float* Wq2      = (const float*)d_in[4];
    const float* Wk       = (const float*)d_in[5];
    const float* Wv       = (const float*)d_in[6];
    const float* lambda_l = (const float*)d_in[7];
    const float* gamma    = (const float*)d_in[8];
    const float* beta     = (const float*)d_in[9];

    k0_qprep<<<BATCH, 256>>>(fp_vec, Wq1, Wq2, Wk);
    k1_stream<<<BATCH*SLICES, K1_THREADS>>>(node_mat, mask);
    k2_epi<<<BATCH, 256>>>(Wv, lambda_l, gamma, beta, (float*)d_out);
}